// round 14
// baseline (speedup 1.0000x reference)
#include <cuda_runtime.h>
#include <cuda_fp16.h>
#include <math.h>
#include <stdint.h>

// Problem constants
#define BATCH 2
#define SEQ   2048
#define DIM   1024
#define HEADS 16
#define DH    64
#define MTOT  (BATCH*SEQ)          // 4096 rows

// Scratch (allocation-free rule: __device__ globals)
__device__ __half g_xh[(size_t)MTOT * DIM];
__device__ __half g_wqkv_h[(size_t)DIM * 3 * DIM];
__device__ __half g_wproj_h[(size_t)DIM * DIM];
__device__ __half g_qkv[(size_t)MTOT * 3 * DIM];
__device__ __half g_attn[(size_t)MTOT * DIM];

// ---------------------------------------------------------------------------
// PTX helpers
// ---------------------------------------------------------------------------
__device__ __forceinline__ uint32_t smem_u32(const void* p) {
    uint32_t a;
    asm("{ .reg .u64 t; cvta.to.shared.u64 t, %1; cvt.u32.u64 %0, t; }" : "=r"(a) : "l"(p));
    return a;
}

__device__ __forceinline__ void ldsm_x4(uint32_t r[4], uint32_t addr) {
    asm volatile("ldmatrix.sync.aligned.m8n8.x4.shared.b16 {%0,%1,%2,%3}, [%4];"
                 : "=r"(r[0]), "=r"(r[1]), "=r"(r[2]), "=r"(r[3]) : "r"(addr));
}
__device__ __forceinline__ void ldsm_x4t(uint32_t r[4], uint32_t addr) {
    asm volatile("ldmatrix.sync.aligned.m8n8.x4.trans.shared.b16 {%0,%1,%2,%3}, [%4];"
                 : "=r"(r[0]), "=r"(r[1]), "=r"(r[2]), "=r"(r[3]) : "r"(addr));
}
__device__ __forceinline__ void mma_f16(float c[4], const uint32_t a[4],
                                        uint32_t b0, uint32_t b1) {
    asm volatile(
        "mma.sync.aligned.m16n8k16.row.col.f32.f16.f16.f32 "
        "{%0,%1,%2,%3}, {%4,%5,%6,%7}, {%8,%9}, {%0,%1,%2,%3};"
        : "+f"(c[0]), "+f"(c[1]), "+f"(c[2]), "+f"(c[3])
        : "r"(a[0]), "r"(a[1]), "r"(a[2]), "r"(a[3]), "r"(b0), "r"(b1));
}
__device__ __forceinline__ float ex2f(float x) {
    float r;
    asm("ex2.approx.ftz.f32 %0, %1;" : "=f"(r) : "f"(x));
    return r;
}

#define CP_A16(dst, src) \
    asm volatile("cp.async.cg.shared.global [%0], [%1], 16;" :: "r"(dst), "l"(src))
#define CP_COMMIT() asm volatile("cp.async.commit_group;" ::: "memory")
#define CP_WAIT(n)  asm volatile("cp.async.wait_group %0;" :: "n"(n) : "memory")

// ---------------------------------------------------------------------------
// fp32 -> fp16 conversion pre-pass
// ---------------------------------------------------------------------------
__global__ __launch_bounds__(256) void cvt_half_kernel(const float4* __restrict__ in,
                                                       uint2* __restrict__ out) {
    int i = blockIdx.x * 256 + threadIdx.x;
    float4 v = in[i];
    __half2 a = __floats2half2_rn(v.x, v.y);
    __half2 b = __floats2half2_rn(v.z, v.w);
    out[i] = make_uint2(*(uint32_t*)&a, *(uint32_t*)&b);
}

// ---------------------------------------------------------------------------
// FP16 tensor-core GEMM v5: 128 threads, 4 warps (2m x 2n), warp tile 64x64.
// Deep per-warp ILP: all 16 ldsm for the chunk issued up front (both k-slices
// register-resident), then 64 back-to-back independent HMMA.
// 3-stage cp.async pipeline. 2 CTAs/SM (<=256 regs/thread at 128 thr).
// ---------------------------------------------------------------------------
#define HAK 40
#define HBN 136
#define NST 3

template <bool HALF_OUT>
__global__ __launch_bounds__(128, 2) void hgemm(const __half* __restrict__ A,
                                                const __half* __restrict__ B,
                                                void* __restrict__ Cv,
                                                int N, int K) {
    __shared__ __half As[NST][128][HAK];
    __shared__ __half Bs[NST][32][HBN];

    const int tid  = threadIdx.x;
    const int lane = tid & 31;
    const int wid  = tid >> 5;
    const int wm   = wid & 1;        // m offset wm*64
    const int wn   = wid >> 1;       // n offset wn*64
    const int g    = lane >> 2;
    const int q    = lane & 3;

    const int m0 = blockIdx.y * 128;
    const int n0 = blockIdx.x * 128;

    float acc[4][8][4];
#pragma unroll
    for (int i = 0; i < 4; i++)
#pragma unroll
        for (int j = 0; j < 8; j++)
#pragma unroll
            for (int r = 0; r < 4; r++) acc[i][j][r] = 0.f;

    const int NC = K / 32;

    const uint32_t aBase = smem_u32(&As[0][0][0]);
    const uint32_t bBase = smem_u32(&Bs[0][0][0]);
    const uint32_t stageA = 128 * HAK * 2;
    const uint32_t stageB = 32 * HBN * 2;

    const int l15 = lane & 15, lhi = lane >> 4;
    const uint32_t aAddr = aBase + (uint32_t)(((wm * 64 + l15) * HAK + lhi * 8) * 2);
    const uint32_t bAddr = bBase + (uint32_t)((l15 * HBN + wn * 64 + lhi * 8) * 2);

    const __half* Arow = A + (size_t)(m0 + tid) * K;
    auto ld_async = [&](int c, int s) {
        const __half* asrc = Arow + c * 32;
        uint32_t adst = aBase + s * stageA + (uint32_t)(tid * HAK * 2);
#pragma unroll
        for (int i = 0; i < 4; i++)
            CP_A16(adst + i * 16, asrc + i * 8);
#pragma unroll
        for (int i = 0; i < 4; i++) {
            int idx = tid + i * 128;
            int row = idx >> 4, ch = idx & 15;
            const __half* bsrc = B + (size_t)(c * 32 + row) * N + n0 + ch * 8;
            uint32_t bdst = bBase + s * stageB + (uint32_t)((row * HBN + ch * 8) * 2);
            CP_A16(bdst, bsrc);
        }
    };

    ld_async(0, 0); CP_COMMIT();
    ld_async(1, 1); CP_COMMIT();

    for (int c = 0; c < NC; c++) {
        const int s = c % NST;
        if (c + 1 < NC) { CP_WAIT(1); } else { CP_WAIT(0); }
        __syncthreads();
        if (c + 2 < NC) { ld_async(c + 2, (c + 2) % NST); CP_COMMIT(); }

        // ---- issue ALL fragment loads for this chunk (both k-slices) ----
        uint32_t afr[2][4][4], bfr[2][4][4];
#pragma unroll
        for (int ks = 0; ks < 2; ks++) {
#pragma unroll
            for (int mt = 0; mt < 4; mt++)
                ldsm_x4(afr[ks][mt], aAddr + s * stageA + ks * 32 + mt * (16 * HAK * 2));
#pragma unroll
            for (int nbp = 0; nbp < 4; nbp++)
                ldsm_x4t(bfr[ks][nbp], bAddr + s * stageB + ks * (16 * HBN * 2) + nbp * 32);
        }

        // ---- 64 independent HMMA back-to-back ----
#pragma unroll
        for (int ks = 0; ks < 2; ks++)
#pragma unroll
            for (int nbp = 0; nbp < 4; nbp++)
#pragma unroll
                for (int mt = 0; mt < 4; mt++) {
                    mma_f16(acc[mt][2 * nbp],     afr[ks][mt], bfr[ks][nbp][0], bfr[ks][nbp][1]);
                    mma_f16(acc[mt][2 * nbp + 1], afr[ks][mt], bfr[ks][nbp][2], bfr[ks][nbp][3]);
                }
    }

    // epilogue: warp writes its 64x64 tile
#pragma unroll
    for (int mt = 0; mt < 4; mt++) {
        int r0 = m0 + wm * 64 + mt * 16 + g;
#pragma unroll
        for (int nt = 0; nt < 8; nt++) {
            int c0 = n0 + wn * 64 + nt * 8 + q * 2;
            if (HALF_OUT) {
                __half* C = (__half*)Cv;
                *(__half2*)&C[(size_t)r0 * N + c0] =
                    __floats2half2_rn(acc[mt][nt][0], acc[mt][nt][1]);
                *(__half2*)&C[(size_t)(r0 + 8) * N + c0] =
                    __floats2half2_rn(acc[mt][nt][2], acc[mt][nt][3]);
            } else {
                float* C = (float*)Cv;
                *(float2*)&C[(size_t)r0 * N + c0]       = make_float2(acc[mt][nt][0], acc[mt][nt][1]);
                *(float2*)&C[(size_t)(r0 + 8) * N + c0] = make_float2(acc[mt][nt][2], acc[mt][nt][3]);
            }
        }
    }
}

// ---------------------------------------------------------------------------
// Flash attention, fp16 mma + ldmatrix + fragment double-buffering,
// triple-buffered cp.async K/V tiles. One CTA per (q-tile, b, h).
// ---------------------------------------------------------------------------
#define FST 72
#define NQT (SEQ/128)
#define KVST (2 * 64 * FST)   // halves per KV stage (K then V)
#define FLASH_SMEM ((128*FST + 3*KVST + 4*32*FST) * 2)

__global__ __launch_bounds__(128, 2) void flash_f16(const __half* __restrict__ qkv,
                                                    __half* __restrict__ attn_out) {
    extern __shared__ __half smh[];
    __half* Qs = smh;
    __half* KV = Qs + 128 * FST;
    __half* Ps = KV + 3 * KVST;

    const int tid  = threadIdx.x;
    const int lane = tid & 31;
    const int w    = tid >> 5;
    const int g    = lane >> 2;
    const int q    = lane & 3;

    const int bh = blockIdx.y;
    const int b  = bh >> 4;
    const int h  = bh & 15;

    const float LOG2E  = 1.44269504088896f;
    const float scale2 = 0.125f * LOG2E;
    const float slope2 = exp2f(-0.5f * (float)(h + 1)) * LOG2E;

    const __half* qb = qkv + (size_t)b * SEQ * (3 * DIM) + h * DH;
    const __half* kb = qb + DIM;
    const __half* vb = qb + 2 * DIM;

    __half* Pw = Ps + w * 32 * FST;

    const uint32_t sQ = smem_u32(Qs), sKV = smem_u32(KV), sP = smem_u32(Pw);
    const int l15 = lane & 15, lhi = lane >> 4;
    const uint32_t qA = sQ + (uint32_t)(((w * 32 + l15) * FST + lhi * 8) * 2);
    const uint32_t pA = sP + (uint32_t)((l15 * FST + lhi * 8) * 2);
    const uint32_t kBr = sKV + (uint32_t)((((lane & 7) + ((lane >> 4) << 3)) * FST
                                          + ((lane >> 3) & 1) * 8) * 2);
    const uint32_t vBr = sKV + (uint32_t)(64 * FST * 2) +
                         (uint32_t)((l15 * FST + lhi * 8) * 2);

    const int qi = NQT - 1 - blockIdx.x;    // big tiles first
    const int q0 = qi * 128;

    {
        const __half* src = qb + (size_t)(q0 + tid) * (3 * DIM);
        __half* dst = Qs + tid * FST;
#pragma unroll
        for (int c = 0; c < 8; c++)
            *(uint4*)(dst + c * 8) = *(const uint4*)(src + c * 8);
    }

    const int kvr = tid >> 1, kvc = (tid & 1) * 32;
    auto ld_kv = [&](int kt, int s) {
        const int k0_ = kt * 64;
        const __half* ksrc = kb + (size_t)(k0_ + kvr) * (3 * DIM) + kvc;
        const __half* vsrc = vb + (size_t)(k0_ + kvr) * (3 * DIM) + kvc;
        uint32_t kdst = sKV + (uint32_t)(s * KVST * 2) + (uint32_t)((kvr * FST + kvc) * 2);
        uint32_t vdst = kdst + (uint32_t)(64 * FST * 2);
#pragma unroll
        for (int j = 0; j < 4; j++) {
            CP_A16(kdst + j * 16, ksrc + j * 8);
            CP_A16(vdst + j * 16, vsrc + j * 8);
        }
    };

    float o[2][8][4];
    float mprev[2][2], lrun[2][2];
#pragma unroll
    for (int mt = 0; mt < 2; mt++) {
        mprev[mt][0] = mprev[mt][1] = -1e30f;
        lrun[mt][0]  = lrun[mt][1]  = 0.f;
#pragma unroll
        for (int nt = 0; nt < 8; nt++)
#pragma unroll
            for (int r = 0; r < 4; r++) o[mt][nt][r] = 0.f;
    }

    const int nkt = 2 * qi + 2;
    const int wrow_min = q0 + w * 32;
    const int wrow_max = wrow_min + 31;

    ld_kv(0, 0); CP_COMMIT();
    if (nkt > 1) { ld_kv(1, 1); CP_COMMIT(); }

    for (int kt = 0; kt < nkt; kt++) {
        const int s = kt % 3;
        const int k0 = kt * 64;
        if (kt + 1 < nkt) { CP_WAIT(1); } else { CP_WAIT(0); }
        __syncthreads();
        if (kt + 2 < nkt) { ld_kv(kt + 2, (kt + 2) % 3); CP_COMMIT(); }

        if (k0 > wrow_max) continue;

        const uint32_t kB = kBr + (uint32_t)(s * KVST * 2);
        const uint32_t vB = vBr + (uint32_t)(s * KVST * 2);

        // ---- S = Q @ K^T  (fragment double-buffered over ks) ----
        float sreg[2][8][4];
#pragma unroll
        for (int mt = 0; mt < 2; mt++)
#pragma unroll
            for (int nt = 0; nt < 8; nt++)
#pragma unroll
                for (int r = 0; r < 4; r++) sreg[mt][nt][r] = 0.f;

        {
            uint32_t aq[2][2][4], bk4[2][4][4];
            ldsm_x4(aq[0][0], qA);
            ldsm_x4(aq[0][1], qA + 16 * FST * 2);
#pragma unroll
            for (int nbp = 0; nbp < 4; nbp++)
                ldsm_x4(bk4[0][nbp], kB + nbp * 16 * FST * 2);
#pragma unroll
            for (int ks = 0; ks < 4; ks++) {
                const int cur = ks & 1, nxt = cur ^ 1;
                if (ks < 3) {
                    ldsm_x4(aq[nxt][0], qA + (ks + 1) * 32);
                    ldsm_x4(aq[nxt][1], qA + (ks + 1) * 32 + 16 * FST * 2);
#pragma unroll
                    for (int nbp = 0; nbp < 4; nbp++)
                        ldsm_x4(bk4[nxt][nbp], kB + nbp * 16 * FST * 2 + (ks + 1) * 32);
                }
#pragma unroll
                for (int nbp = 0; nbp < 4; nbp++) {
                    mma_f16(sreg[0][2 * nbp],     aq[cur][0], bk4[cur][nbp][0], bk4[cur][nbp][1]);
                    mma_f16(sreg[1][2 * nbp],     aq[cur][1], bk4[cur][nbp][0], bk4[cur][nbp][1]);
                    mma_f16(sreg[0][2 * nbp + 1], aq[cur][0], bk4[cur][nbp][2], bk4[cur][nbp][3]);
                    mma_f16(sreg[1][2 * nbp + 1], aq[cur][1], bk4[cur][nbp][2], bk4[cur][nbp][3]);
                }
            }
        }

        // ---- bias + mask + online softmax (base-2) ----
        const bool need_mask = (k0 + 63 > wrow_min);
#pragma unroll
        for (int mt = 0; mt < 2; mt++) {
            const int r0 = wrow_min + mt * 16 + g;
            const int r1 = r0 + 8;
            float mx0 = -1e30f, mx1 = -1e30f;
#pragma unroll
            for (int nt = 0; nt < 8; nt++) {
#pragma unroll
                for (int jj = 0; jj < 2; jj++) {
                    int col = k0 + nt * 8 + q * 2 + jj;
                    float bias = slope2 * (float)col;
                    float v0 = fmaf(sreg[mt][nt][jj],     scale2, bias);
                    float v1 = fmaf(sreg[mt][nt][2 + jj], scale2, bias);
                    if (need_mask) {
                        if (col > r0) v0 = -1e30f;
                        if (col > r1) v1 = -1e30f;
                    }
                    sreg[mt][nt][jj]     = v0;
                    sreg[mt][nt][2 + jj] = v1;
                    mx0 = fmaxf(mx0, v0);
                    mx1 = fmaxf(mx1, v1);
                }
            }
            mx0 = fmaxf(mx0, __shfl_xor_sync(0xffffffffu, mx0, 1));
            mx0 = fmaxf(mx0, __shfl_xor_sync(0xffffffffu, mx0, 2));
            mx1 = fmaxf(mx1, __shfl_xor_sync(0xffffffffu, mx1, 1));
            mx1 = fmaxf(mx1, __shfl_xor_sync(0xffffffffu, mx1, 2));

            float mn0 = fmaxf(mprev[mt][0], mx0);
            float mn1 = fmaxf(mprev[mt][1], mx1);
            float sum0 = 0.f, sum1 = 0.f;
#pragma unroll
            for (int nt = 0; nt < 8; nt++) {
#pragma unroll
                for (int jj = 0; jj < 2; jj++) {
                    float p0 = ex2f(sreg[mt][nt][jj]     - mn0);
                    float p1 = ex2f(sreg[mt][nt][2 + jj] - mn1);
                    sreg[mt][nt][jj]     = p0;
                    sreg[mt][nt][2 + jj] = p1;
                    sum0 += p0;
                    sum1 += p1;
                }
            }
            sum0 += __shfl_xor_sync(0xffffffffu, sum0, 1);
            sum0 += __shfl_xor_sync(0xffffffffu, sum0, 2);
            sum1 += __shfl_xor_sync(0xffffffffu, sum1, 1);
            sum1 += __shfl_xor_sync(0xffffffffu, sum1, 2);

            float al0 = ex2f(mprev[mt][0] - mn0);
            float al1 = ex2f(mprev[mt][1] - mn1);
            lrun[mt][0] = lrun[mt][0] * al0 + sum0;
            lrun[mt][1] = lrun[mt][1] * al1 + sum1;
            mprev[mt][0] = mn0;
            mprev[mt][1] = mn1;
#pragma unroll
            for (int nt = 0; nt < 8; nt++) {
                o[mt][nt][0] *= al0;
                o[mt][nt][1] *= al0;
                o[mt][nt][2] *= al1;
                o[mt][nt][3] *= al1;
            }

#pragma unroll
            for (int nt = 0; nt < 8; nt++) {
                *(__half2*)&Pw[(mt * 16 + g)     * FST + nt * 8 + q * 2] =
                    __floats2half2_rn(sreg[mt][nt][0], sreg[mt][nt][1]);
                *(__half2*)&Pw[(mt * 16 + g + 8) * FST + nt * 8 + q * 2] =
                    __floats2half2_rn(sreg[mt][nt][2], sreg[mt][nt][3]);
            }
        }
        __syncwarp();

        // ---- O += P @ V  (fragment double-buffered over ks) ----
        {
            uint32_t ap[2][2][4], bv4[2][4][4];
            ldsm_x4(ap[0][0], pA);
            ldsm_x4(ap[0][1], pA + 16 * FST * 2);
#pragma unroll
            for (int nbp = 0; nbp < 4; nbp++)
                ldsm_x4t(bv4[0][nbp], vB + nbp * 32);
#pragma unroll
            for (int ks = 0; ks < 4; ks++) {
                const int cur = ks & 1, nxt = cur ^ 1;
                if (ks < 3) {
                    ldsm_x4(ap[nxt][0], pA + (ks + 1) * 32);
                    ldsm_x4(ap[nxt][1], pA + (ks + 1) * 32 + 16 * FST * 2);
#pragma unroll
                    for (int nbp = 0; nbp < 4; nbp++)
                        ldsm_x4t(bv4[nxt][nbp], vB + (ks + 1) * 16 * FST * 2 + nbp * 32);
                }
#pragma unroll
                for (int nbp = 0; nbp < 4; nbp++) {
                    mma_f16(o[0][2 * nbp],     ap[cur][0], bv4[cur][nbp][0], bv4[cur][nbp][1]);
                    mma_f16(o[1][2 * nbp],     ap[cur][1], bv4[cur][nbp][0], bv4[cur][nbp][1]);
                    mma_f16(o[0][2 * nbp + 1], ap[cur][0], bv4[cur][nbp][2], bv4[cur][nbp][3]);
                    mma_f16(o[1][2 * nbp + 1], ap[cur][1], bv4[cur][nbp][2], bv4[cur][nbp][3]);
                }
            }
        }
    }

    // ---- epilogue ----
#pragma unroll
    for (int mt = 0; mt < 2; mt++) {
        float inv0 = 1.f / lrun[mt][0];
        float inv1 = 1.f / lrun[mt][1];
        int r0 = q0 + w * 32 + mt * 16 + g;
#pragma unroll
        for (int nt = 0; nt < 8; nt++) {
            int c = h * DH + nt * 8 + q * 2;
            *(__half2*)&attn_out[(size_t)(b * SEQ + r0) * DIM + c] =
                __floats2half2_rn(o[mt][nt][0] * inv0, o[mt][nt][1] * inv0);
            *(__half2*)&attn_out[(size_t)(b * SEQ + r0 + 8) * DIM + c] =
                __floats2half2_rn(o[mt][nt][2] * inv1, o[mt][nt][3] * inv1);
        }
    }
}

// ---------------------------------------------------------------------------
extern "C" void kernel_launch(void* const* d_in, const int* in_sizes, int n_in,
                              void* d_out, int out_size) {
    const float* x      = (const float*)d_in[0];
    const float* w_qkv  = (const float*)d_in[1];
    const float* w_proj = (const float*)d_in[2];
    float* out = (float*)d_out;

    __half *xh, *wqkvh, *wprojh, *qkv, *attn;
    cudaGetSymbolAddress((void**)&xh, g_xh);
    cudaGetSymbolAddress((void**)&wqkvh, g_wqkv_h);
    cudaGetSymbolAddress((void**)&wprojh, g_wproj_h);
    cudaGetSymbolAddress((void**)&qkv, g_qkv);
    cudaGetSymbolAddress((void**)&attn, g_attn);

    cudaFuncSetAttribute(flash_f16, cudaFuncAttributeMaxDynamicSharedMemorySize,
                         (int)FLASH_SMEM);

    // 0) convert inputs to half
    cvt_half_kernel<<<(MTOT * DIM) / 1024, 256>>>((const float4*)x, (uint2*)xh);
    cvt_half_kernel<<<(DIM * 3 * DIM) / 1024, 256>>>((const float4*)w_qkv, (uint2*)wqkvh);
    cvt_half_kernel<<<(DIM * DIM) / 1024, 256>>>((const float4*)w_proj, (uint2*)wprojh);

    // 1) qkv = x @ w_qkv  (half out)
    hgemm<true><<<dim3(3 * DIM / 128, MTOT / 128), 128>>>(xh, wqkvh, qkv, 3 * DIM, DIM);

    // 2) attention
    flash_f16<<<dim3(NQT, BATCH * HEADS), 128, FLASH_SMEM>>>(qkv, attn);

    // 3) out = attn @ w_proj  (float out)
    hgemm<false><<<dim3(DIM / 128, MTOT / 128), 128>>>(attn, wprojh, out, DIM, DIM);
}

// round 15
// speedup vs baseline: 1.0780x; 1.0780x over previous
#include <cuda_runtime.h>
#include <cuda_fp16.h>
#include <math.h>
#include <stdint.h>

// Problem constants
#define BATCH 2
#define SEQ   2048
#define DIM   1024
#define HEADS 16
#define DH    64
#define MTOT  (BATCH*SEQ)          // 4096 rows

// Scratch (allocation-free rule: __device__ globals)
__device__ __half g_xh[(size_t)MTOT * DIM];
__device__ __half g_wqkv_h[(size_t)DIM * 3 * DIM];
__device__ __half g_wproj_h[(size_t)DIM * DIM];
__device__ __half g_qkv[(size_t)MTOT * 3 * DIM];
__device__ __half g_attn[(size_t)MTOT * DIM];

// ---------------------------------------------------------------------------
// PTX helpers
// ---------------------------------------------------------------------------
__device__ __forceinline__ uint32_t smem_u32(const void* p) {
    uint32_t a;
    asm("{ .reg .u64 t; cvta.to.shared.u64 t, %1; cvt.u32.u64 %0, t; }" : "=r"(a) : "l"(p));
    return a;
}

__device__ __forceinline__ void ldsm_x4(uint32_t r[4], uint32_t addr) {
    asm volatile("ldmatrix.sync.aligned.m8n8.x4.shared.b16 {%0,%1,%2,%3}, [%4];"
                 : "=r"(r[0]), "=r"(r[1]), "=r"(r[2]), "=r"(r[3]) : "r"(addr));
}
__device__ __forceinline__ void ldsm_x4t(uint32_t r[4], uint32_t addr) {
    asm volatile("ldmatrix.sync.aligned.m8n8.x4.trans.shared.b16 {%0,%1,%2,%3}, [%4];"
                 : "=r"(r[0]), "=r"(r[1]), "=r"(r[2]), "=r"(r[3]) : "r"(addr));
}
__device__ __forceinline__ void mma_f16(float c[4], const uint32_t a[4],
                                        uint32_t b0, uint32_t b1) {
    asm volatile(
        "mma.sync.aligned.m16n8k16.row.col.f32.f16.f16.f32 "
        "{%0,%1,%2,%3}, {%4,%5,%6,%7}, {%8,%9}, {%0,%1,%2,%3};"
        : "+f"(c[0]), "+f"(c[1]), "+f"(c[2]), "+f"(c[3])
        : "r"(a[0]), "r"(a[1]), "r"(a[2]), "r"(a[3]), "r"(b0), "r"(b1));
}
__device__ __forceinline__ float ex2f(float x) {
    float r;
    asm("ex2.approx.ftz.f32 %0, %1;" : "=f"(r) : "f"(x));
    return r;
}

#define CP_A16(dst, src) \
    asm volatile("cp.async.cg.shared.global [%0], [%1], 16;" :: "r"(dst), "l"(src))
#define CP_COMMIT() asm volatile("cp.async.commit_group;" ::: "memory")
#define CP_WAIT(n)  asm volatile("cp.async.wait_group %0;" :: "n"(n) : "memory")

// ---------------------------------------------------------------------------
// fp32 -> fp16 conversion pre-pass
// ---------------------------------------------------------------------------
__global__ __launch_bounds__(256) void cvt_half_kernel(const float4* __restrict__ in,
                                                       uint2* __restrict__ out) {
    int i = blockIdx.x * 256 + threadIdx.x;
    float4 v = in[i];
    __half2 a = __floats2half2_rn(v.x, v.y);
    __half2 b = __floats2half2_rn(v.z, v.w);
    out[i] = make_uint2(*(uint32_t*)&a, *(uint32_t*)&b);
}

// ---------------------------------------------------------------------------
// FP16 tensor-core GEMM v6: 256 threads, 8 warps (2m x 4n), warp tile 64x32.
// BK=64 (double chunk): halves barrier count, doubles HMMA burst length.
// 2-stage cp.async buffering, ldmatrix fragments. 2 CTAs/SM.
// ---------------------------------------------------------------------------
#define HAK 72     // 64 + 8 pad halves (36 words, conflict-free ldsm phases)
#define HBN 136
#define NST 2
#define BKC 64

template <bool HALF_OUT>
__global__ __launch_bounds__(256, 2) void hgemm(const __half* __restrict__ A,
                                                const __half* __restrict__ B,
                                                void* __restrict__ Cv,
                                                int N, int K) {
    __shared__ __half As[NST][128][HAK];   // [m][k]
    __shared__ __half Bs[NST][BKC][HBN];   // [k][n]

    const int tid  = threadIdx.x;
    const int lane = tid & 31;
    const int wid  = tid >> 5;
    const int wm   = wid & 1;        // m offset wm*64
    const int wn   = wid >> 1;       // n offset wn*32 (0..3)
    const int g    = lane >> 2;
    const int q    = lane & 3;

    const int m0 = blockIdx.y * 128;
    const int n0 = blockIdx.x * 128;

    float acc[4][4][4];              // [mt 16-row][nt 8-col][frag]
#pragma unroll
    for (int i = 0; i < 4; i++)
#pragma unroll
        for (int j = 0; j < 4; j++)
#pragma unroll
            for (int r = 0; r < 4; r++) acc[i][j][r] = 0.f;

    const int NC = K / BKC;

    const uint32_t aBase = smem_u32(&As[0][0][0]);
    const uint32_t bBase = smem_u32(&Bs[0][0][0]);
    const uint32_t stageA = 128 * HAK * 2;
    const uint32_t stageB = BKC * HBN * 2;

    const int l15 = lane & 15, lhi = lane >> 4;
    const uint32_t aAddr = aBase + (uint32_t)(((wm * 64 + l15) * HAK + lhi * 8) * 2);
    const uint32_t bAddr = bBase + (uint32_t)((l15 * HBN + wn * 32 + lhi * 8) * 2);

    // loaders: 256 threads
    // A tile: 128 rows x 64 halves = 1024 x 16B chunks -> 4 per thread
    const int arow = tid >> 1;                 // row 0..127
    const int ach  = (tid & 1) * 32;           // col halves 0/32
    const __half* Arow = A + (size_t)(m0 + arow) * K + ach;
    auto ld_async = [&](int c, int s) {
        const __half* asrc = Arow + c * BKC;
        uint32_t adst = aBase + s * stageA + (uint32_t)((arow * HAK + ach) * 2);
#pragma unroll
        for (int i = 0; i < 4; i++)
            CP_A16(adst + i * 16, asrc + i * 8);
        // B tile: 64 rows x 128 halves = 1024 x 16B chunks -> 4 per thread
#pragma unroll
        for (int i = 0; i < 4; i++) {
            int idx = tid + i * 256;
            int row = idx >> 4, ch = idx & 15;
            const __half* bsrc = B + (size_t)(c * BKC + row) * N + n0 + ch * 8;
            uint32_t bdst = bBase + s * stageB + (uint32_t)((row * HBN + ch * 8) * 2);
            CP_A16(bdst, bsrc);
        }
    };

    ld_async(0, 0); CP_COMMIT();

    for (int c = 0; c < NC; c++) {
        const int s = c & 1;
        CP_WAIT(0);
        __syncthreads();
        if (c + 1 < NC) { ld_async(c + 1, s ^ 1); CP_COMMIT(); }

#pragma unroll
        for (int ks = 0; ks < 4; ks++) {
            uint32_t afr[4][4];
#pragma unroll
            for (int mt = 0; mt < 4; mt++)
                ldsm_x4(afr[mt], aAddr + s * stageA + ks * 32 + mt * (16 * HAK * 2));
#pragma unroll
            for (int nbp = 0; nbp < 2; nbp++) {
                uint32_t b4[4];
                ldsm_x4t(b4, bAddr + s * stageB + ks * (16 * HBN * 2) + nbp * 32);
#pragma unroll
                for (int mt = 0; mt < 4; mt++) {
                    mma_f16(acc[mt][2 * nbp],     afr[mt], b4[0], b4[1]);
                    mma_f16(acc[mt][2 * nbp + 1], afr[mt], b4[2], b4[3]);
                }
            }
        }
    }

    // epilogue: warp writes its 64x32 tile
#pragma unroll
    for (int mt = 0; mt < 4; mt++) {
        int r0 = m0 + wm * 64 + mt * 16 + g;
#pragma unroll
        for (int nt = 0; nt < 4; nt++) {
            int c0 = n0 + wn * 32 + nt * 8 + q * 2;
            if (HALF_OUT) {
                __half* C = (__half*)Cv;
                *(__half2*)&C[(size_t)r0 * N + c0] =
                    __floats2half2_rn(acc[mt][nt][0], acc[mt][nt][1]);
                *(__half2*)&C[(size_t)(r0 + 8) * N + c0] =
                    __floats2half2_rn(acc[mt][nt][2], acc[mt][nt][3]);
            } else {
                float* C = (float*)Cv;
                *(float2*)&C[(size_t)r0 * N + c0]       = make_float2(acc[mt][nt][0], acc[mt][nt][1]);
                *(float2*)&C[(size_t)(r0 + 8) * N + c0] = make_float2(acc[mt][nt][2], acc[mt][nt][3]);
            }
        }
    }
}

// ---------------------------------------------------------------------------
// Flash attention (byte-identical to R12 best): fp16 mma + ldmatrix,
// triple-buffered cp.async K/V tiles. One CTA per (q-tile, b, h).
// ---------------------------------------------------------------------------
#define FST 72
#define NQT (SEQ/128)
#define KVST (2 * 64 * FST)   // halves per KV stage (K then V)
#define FLASH_SMEM ((128*FST + 3*KVST + 4*32*FST) * 2)

__global__ __launch_bounds__(128) void flash_f16(const __half* __restrict__ qkv,
                                                 __half* __restrict__ attn_out) {
    extern __shared__ __half smh[];
    __half* Qs = smh;
    __half* KV = Qs + 128 * FST;
    __half* Ps = KV + 3 * KVST;

    const int tid  = threadIdx.x;
    const int lane = tid & 31;
    const int w    = tid >> 5;
    const int g    = lane >> 2;
    const int q    = lane & 3;

    const int bh = blockIdx.y;
    const int b  = bh >> 4;
    const int h  = bh & 15;

    const float LOG2E  = 1.44269504088896f;
    const float scale2 = 0.125f * LOG2E;
    const float slope2 = exp2f(-0.5f * (float)(h + 1)) * LOG2E;

    const __half* qb = qkv + (size_t)b * SEQ * (3 * DIM) + h * DH;
    const __half* kb = qb + DIM;
    const __half* vb = qb + 2 * DIM;

    __half* Pw = Ps + w * 32 * FST;

    const uint32_t sQ = smem_u32(Qs), sKV = smem_u32(KV), sP = smem_u32(Pw);
    const int l15 = lane & 15, lhi = lane >> 4;
    const uint32_t qA = sQ + (uint32_t)(((w * 32 + l15) * FST + lhi * 8) * 2);
    const uint32_t pA = sP + (uint32_t)((l15 * FST + lhi * 8) * 2);
    const uint32_t kBr = sKV + (uint32_t)((((lane & 7) + ((lane >> 4) << 3)) * FST
                                          + ((lane >> 3) & 1) * 8) * 2);
    const uint32_t vBr = sKV + (uint32_t)(64 * FST * 2) +
                         (uint32_t)((l15 * FST + lhi * 8) * 2);

    const int qi = NQT - 1 - blockIdx.x;    // big tiles first
    const int q0 = qi * 128;

    {
        const __half* src = qb + (size_t)(q0 + tid) * (3 * DIM);
        __half* dst = Qs + tid * FST;
#pragma unroll
        for (int c = 0; c < 8; c++)
            *(uint4*)(dst + c * 8) = *(const uint4*)(src + c * 8);
    }

    const int kvr = tid >> 1, kvc = (tid & 1) * 32;
    auto ld_kv = [&](int kt, int s) {
        const int k0_ = kt * 64;
        const __half* ksrc = kb + (size_t)(k0_ + kvr) * (3 * DIM) + kvc;
        const __half* vsrc = vb + (size_t)(k0_ + kvr) * (3 * DIM) + kvc;
        uint32_t kdst = sKV + (uint32_t)(s * KVST * 2) + (uint32_t)((kvr * FST + kvc) * 2);
        uint32_t vdst = kdst + (uint32_t)(64 * FST * 2);
#pragma unroll
        for (int j = 0; j < 4; j++) {
            CP_A16(kdst + j * 16, ksrc + j * 8);
            CP_A16(vdst + j * 16, vsrc + j * 8);
        }
    };

    float o[2][8][4];
    float mprev[2][2], lrun[2][2];
#pragma unroll
    for (int mt = 0; mt < 2; mt++) {
        mprev[mt][0] = mprev[mt][1] = -1e30f;
        lrun[mt][0]  = lrun[mt][1]  = 0.f;
#pragma unroll
        for (int nt = 0; nt < 8; nt++)
#pragma unroll
            for (int r = 0; r < 4; r++) o[mt][nt][r] = 0.f;
    }

    const int nkt = 2 * qi + 2;
    const int wrow_min = q0 + w * 32;
    const int wrow_max = wrow_min + 31;

    ld_kv(0, 0); CP_COMMIT();
    if (nkt > 1) { ld_kv(1, 1); CP_COMMIT(); }

    for (int kt = 0; kt < nkt; kt++) {
        const int s = kt % 3;
        const int k0 = kt * 64;
        if (kt + 1 < nkt) { CP_WAIT(1); } else { CP_WAIT(0); }
        __syncthreads();
        if (kt + 2 < nkt) { ld_kv(kt + 2, (kt + 2) % 3); CP_COMMIT(); }

        if (k0 > wrow_max) continue;

        const uint32_t kB = kBr + (uint32_t)(s * KVST * 2);
        const uint32_t vB = vBr + (uint32_t)(s * KVST * 2);

        float sreg[2][8][4];
#pragma unroll
        for (int mt = 0; mt < 2; mt++)
#pragma unroll
            for (int nt = 0; nt < 8; nt++)
#pragma unroll
                for (int r = 0; r < 4; r++) sreg[mt][nt][r] = 0.f;

#pragma unroll
        for (int ks = 0; ks < 4; ks++) {
            uint32_t afr[2][4];
            ldsm_x4(afr[0], qA + ks * 32);
            ldsm_x4(afr[1], qA + ks * 32 + 16 * FST * 2);
#pragma unroll
            for (int nbp = 0; nbp < 4; nbp++) {
                uint32_t b4[4];
                ldsm_x4(b4, kB + nbp * 16 * FST * 2 + ks * 32);
                mma_f16(sreg[0][2 * nbp],     afr[0], b4[0], b4[1]);
                mma_f16(sreg[1][2 * nbp],     afr[1], b4[0], b4[1]);
                mma_f16(sreg[0][2 * nbp + 1], afr[0], b4[2], b4[3]);
                mma_f16(sreg[1][2 * nbp + 1], afr[1], b4[2], b4[3]);
            }
        }

        const bool need_mask = (k0 + 63 > wrow_min);
#pragma unroll
        for (int mt = 0; mt < 2; mt++) {
            const int r0 = wrow_min + mt * 16 + g;
            const int r1 = r0 + 8;
            float mx0 = -1e30f, mx1 = -1e30f;
#pragma unroll
            for (int nt = 0; nt < 8; nt++) {
#pragma unroll
                for (int jj = 0; jj < 2; jj++) {
                    int col = k0 + nt * 8 + q * 2 + jj;
                    float bias = slope2 * (float)col;
                    float v0 = fmaf(sreg[mt][nt][jj],     scale2, bias);
                    float v1 = fmaf(sreg[mt][nt][2 + jj], scale2, bias);
                    if (need_mask) {
                        if (col > r0) v0 = -1e30f;
                        if (col > r1) v1 = -1e30f;
                    }
                    sreg[mt][nt][jj]     = v0;
                    sreg[mt][nt][2 + jj] = v1;
                    mx0 = fmaxf(mx0, v0);
                    mx1 = fmaxf(mx1, v1);
                }
            }
            mx0 = fmaxf(mx0, __shfl_xor_sync(0xffffffffu, mx0, 1));
            mx0 = fmaxf(mx0, __shfl_xor_sync(0xffffffffu, mx0, 2));
            mx1 = fmaxf(mx1, __shfl_xor_sync(0xffffffffu, mx1, 1));
            mx1 = fmaxf(mx1, __shfl_xor_sync(0xffffffffu, mx1, 2));

            float mn0 = fmaxf(mprev[mt][0], mx0);
            float mn1 = fmaxf(mprev[mt][1], mx1);
            float sum0 = 0.f, sum1 = 0.f;
#pragma unroll
            for (int nt = 0; nt < 8; nt++) {
#pragma unroll
                for (int jj = 0; jj < 2; jj++) {
                    float p0 = ex2f(sreg[mt][nt][jj]     - mn0);
                    float p1 = ex2f(sreg[mt][nt][2 + jj] - mn1);
                    sreg[mt][nt][jj]     = p0;
                    sreg[mt][nt][2 + jj] = p1;
                    sum0 += p0;
                    sum1 += p1;
                }
            }
            sum0 += __shfl_xor_sync(0xffffffffu, sum0, 1);
            sum0 += __shfl_xor_sync(0xffffffffu, sum0, 2);
            sum1 += __shfl_xor_sync(0xffffffffu, sum1, 1);
            sum1 += __shfl_xor_sync(0xffffffffu, sum1, 2);

            float al0 = ex2f(mprev[mt][0] - mn0);
            float al1 = ex2f(mprev[mt][1] - mn1);
            lrun[mt][0] = lrun[mt][0] * al0 + sum0;
            lrun[mt][1] = lrun[mt][1] * al1 + sum1;
            mprev[mt][0] = mn0;
            mprev[mt][1] = mn1;
#pragma unroll
            for (int nt = 0; nt < 8; nt++) {
                o[mt][nt][0] *= al0;
                o[mt][nt][1] *= al0;
                o[mt][nt][2] *= al1;
                o[mt][nt][3] *= al1;
            }

#pragma unroll
            for (int nt = 0; nt < 8; nt++) {
                *(__half2*)&Pw[(mt * 16 + g)     * FST + nt * 8 + q * 2] =
                    __floats2half2_rn(sreg[mt][nt][0], sreg[mt][nt][1]);
                *(__half2*)&Pw[(mt * 16 + g + 8) * FST + nt * 8 + q * 2] =
                    __floats2half2_rn(sreg[mt][nt][2], sreg[mt][nt][3]);
            }
        }
        __syncwarp();

#pragma unroll
        for (int ks = 0; ks < 4; ks++) {
            uint32_t afr[2][4];
            ldsm_x4(afr[0], pA + ks * 32);
            ldsm_x4(afr[1], pA + ks * 32 + 16 * FST * 2);
#pragma unroll
            for (int nbp = 0; nbp < 4; nbp++) {
                uint32_t b4[4];
                ldsm_x4t(b4, vB + ks * 16 * FST * 2 + nbp * 32);
                mma_f16(o[0][2 * nbp],     afr[0], b4[0], b4[1]);
                mma_f16(o[1][2 * nbp],     afr[1], b4[0], b4[1]);
                mma_f16(o[0][2 * nbp + 1], afr[0], b4[2], b4[3]);
                mma_f16(o[1][2 * nbp + 1], afr[1], b4[2], b4[3]);
            }
        }
    }

#pragma unroll
    for (int mt = 0; mt < 2; mt++) {
        float inv0 = 1.f / lrun[mt][0];
        float inv1 = 1.f / lrun[mt][1];
        int r0 = q0 + w * 32 + mt * 16 + g;
#pragma unroll
        for (int nt = 0; nt < 8; nt++) {
            int c = h * DH + nt * 8 + q * 2;
            *(__half2*)&attn_out[(size_t)(b * SEQ + r0) * DIM + c] =
                __floats2half2_rn(o[mt][nt][0] * inv0, o[mt][nt][1] * inv0);
            *(__half2*)&attn_out[(size_t)(b * SEQ + r0 + 8) * DIM + c] =
                __floats2half2_rn(o[mt][nt][2] * inv1, o[mt][nt][3] * inv1);
        }
    }
}

// ---------------------------------------------------------------------------
extern "C" void kernel_launch(void* const* d_in, const int* in_sizes, int n_in,
                              void* d_out, int out_size) {
    const float* x      = (const float*)d_in[0];
    const float* w_qkv  = (const float*)d_in[1];
    const float* w_proj = (const float*)d_in[2];
    float* out = (float*)d_out;

    __half *xh, *wqkvh, *wprojh, *qkv, *attn;
    cudaGetSymbolAddress((void**)&xh, g_xh);
    cudaGetSymbolAddress((void**)&wqkvh, g_wqkv_h);
    cudaGetSymbolAddress((void**)&wprojh, g_wproj_h);
    cudaGetSymbolAddress((void**)&qkv, g_qkv);
    cudaGetSymbolAddress((void**)&attn, g_attn);

    cudaFuncSetAttribute(flash_f16, cudaFuncAttributeMaxDynamicSharedMemorySize,
                         (int)FLASH_SMEM);

    // 0) convert inputs to half
    cvt_half_kernel<<<(MTOT * DIM) / 1024, 256>>>((const float4*)x, (uint2*)xh);
    cvt_half_kernel<<<(DIM * 3 * DIM) / 1024, 256>>>((const float4*)w_qkv, (uint2*)wqkvh);
    cvt_half_kernel<<<(DIM * DIM) / 1024, 256>>>((const float4*)w_proj, (uint2*)wprojh);

    // 1) qkv = x @ w_qkv  (half out)
    hgemm<true><<<dim3(3 * DIM / 128, MTOT / 128), 256>>>(xh, wqkvh, qkv, 3 * DIM, DIM);

    // 2) attention
    flash_f16<<<dim3(NQT, BATCH * HEADS), 128, FLASH_SMEM>>>(qkv, attn);

    // 3) out = attn @ w_proj  (float out)
    hgemm<false><<<dim3(DIM / 128, MTOT / 128), 256>>>(attn, wprojh, out, DIM, DIM);
}

// round 16
// speedup vs baseline: 1.0880x; 1.0093x over previous
#include <cuda_runtime.h>
#include <cuda_fp16.h>
#include <math.h>
#include <stdint.h>

// Problem constants
#define BATCH 2
#define SEQ   2048
#define DIM   1024
#define HEADS 16
#define DH    64
#define MTOT  (BATCH*SEQ)          // 4096 rows

// Scratch (allocation-free rule: __device__ globals)
__device__ __half g_xh[(size_t)MTOT * DIM];
__device__ __half g_wqkv_h[(size_t)DIM * 3 * DIM];
__device__ __half g_wproj_h[(size_t)DIM * DIM];
__device__ __half g_qkv[(size_t)MTOT * 3 * DIM];
__device__ __half g_attn[(size_t)MTOT * DIM];

// ---------------------------------------------------------------------------
// PTX helpers
// ---------------------------------------------------------------------------
__device__ __forceinline__ uint32_t smem_u32(const void* p) {
    uint32_t a;
    asm("{ .reg .u64 t; cvta.to.shared.u64 t, %1; cvt.u32.u64 %0, t; }" : "=r"(a) : "l"(p));
    return a;
}

__device__ __forceinline__ void ldsm_x4(uint32_t r[4], uint32_t addr) {
    asm volatile("ldmatrix.sync.aligned.m8n8.x4.shared.b16 {%0,%1,%2,%3}, [%4];"
                 : "=r"(r[0]), "=r"(r[1]), "=r"(r[2]), "=r"(r[3]) : "r"(addr));
}
__device__ __forceinline__ void ldsm_x4t(uint32_t r[4], uint32_t addr) {
    asm volatile("ldmatrix.sync.aligned.m8n8.x4.trans.shared.b16 {%0,%1,%2,%3}, [%4];"
                 : "=r"(r[0]), "=r"(r[1]), "=r"(r[2]), "=r"(r[3]) : "r"(addr));
}
__device__ __forceinline__ void mma_f16(float c[4], const uint32_t a[4],
                                        uint32_t b0, uint32_t b1) {
    asm volatile(
        "mma.sync.aligned.m16n8k16.row.col.f32.f16.f16.f32 "
        "{%0,%1,%2,%3}, {%4,%5,%6,%7}, {%8,%9}, {%0,%1,%2,%3};"
        : "+f"(c[0]), "+f"(c[1]), "+f"(c[2]), "+f"(c[3])
        : "r"(a[0]), "r"(a[1]), "r"(a[2]), "r"(a[3]), "r"(b0), "r"(b1));
}
__device__ __forceinline__ float ex2f(float x) {
    float r;
    asm("ex2.approx.ftz.f32 %0, %1;" : "=f"(r) : "f"(x));
    return r;
}
// pack (lo,hi) fp32 pair -> f16x2, then exp2 in half2 (one MUFU op per 2 els)
__device__ __forceinline__ uint32_t ex2_h2(float hi, float lo) {
    uint32_t h;
    asm("{\n\tcvt.rn.f16x2.f32 %0, %1, %2;\n\tex2.approx.f16x2 %0, %0;\n\t}"
        : "=r"(h) : "f"(hi), "f"(lo));
    return h;
}

#define CP_A16(dst, src) \
    asm volatile("cp.async.cg.shared.global [%0], [%1], 16;" :: "r"(dst), "l"(src))
#define CP_COMMIT() asm volatile("cp.async.commit_group;" ::: "memory")
#define CP_WAIT(n)  asm volatile("cp.async.wait_group %0;" :: "n"(n) : "memory")

// ---------------------------------------------------------------------------
// fp32 -> fp16 conversion pre-pass
// ---------------------------------------------------------------------------
__global__ __launch_bounds__(256) void cvt_half_kernel(const float4* __restrict__ in,
                                                       uint2* __restrict__ out) {
    int i = blockIdx.x * 256 + threadIdx.x;
    float4 v = in[i];
    __half2 a = __floats2half2_rn(v.x, v.y);
    __half2 b = __floats2half2_rn(v.z, v.w);
    out[i] = make_uint2(*(uint32_t*)&a, *(uint32_t*)&b);
}

// ---------------------------------------------------------------------------
// FP16 tensor-core GEMM (best known, R14): 256 threads, 8 warps (2m x 4n),
// warp tile 64x32, BK=64, 2-stage cp.async. FROZEN.
// ---------------------------------------------------------------------------
#define HAK 72
#define HBN 136
#define NST 2
#define BKC 64

template <bool HALF_OUT>
__global__ __launch_bounds__(256, 2) void hgemm(const __half* __restrict__ A,
                                                const __half* __restrict__ B,
                                                void* __restrict__ Cv,
                                                int N, int K) {
    __shared__ __half As[NST][128][HAK];   // [m][k]
    __shared__ __half Bs[NST][BKC][HBN];   // [k][n]

    const int tid  = threadIdx.x;
    const int lane = tid & 31;
    const int wid  = tid >> 5;
    const int wm   = wid & 1;
    const int wn   = wid >> 1;
    const int g    = lane >> 2;
    const int q    = lane & 3;

    const int m0 = blockIdx.y * 128;
    const int n0 = blockIdx.x * 128;

    float acc[4][4][4];
#pragma unroll
    for (int i = 0; i < 4; i++)
#pragma unroll
        for (int j = 0; j < 4; j++)
#pragma unroll
            for (int r = 0; r < 4; r++) acc[i][j][r] = 0.f;

    const int NC = K / BKC;

    const uint32_t aBase = smem_u32(&As[0][0][0]);
    const uint32_t bBase = smem_u32(&Bs[0][0][0]);
    const uint32_t stageA = 128 * HAK * 2;
    const uint32_t stageB = BKC * HBN * 2;

    const int l15 = lane & 15, lhi = lane >> 4;
    const uint32_t aAddr = aBase + (uint32_t)(((wm * 64 + l15) * HAK + lhi * 8) * 2);
    const uint32_t bAddr = bBase + (uint32_t)((l15 * HBN + wn * 32 + lhi * 8) * 2);

    const int arow = tid >> 1;
    const int ach  = (tid & 1) * 32;
    const __half* Arow = A + (size_t)(m0 + arow) * K + ach;
    auto ld_async = [&](int c, int s) {
        const __half* asrc = Arow + c * BKC;
        uint32_t adst = aBase + s * stageA + (uint32_t)((arow * HAK + ach) * 2);
#pragma unroll
        for (int i = 0; i < 4; i++)
            CP_A16(adst + i * 16, asrc + i * 8);
#pragma unroll
        for (int i = 0; i < 4; i++) {
            int idx = tid + i * 256;
            int row = idx >> 4, ch = idx & 15;
            const __half* bsrc = B + (size_t)(c * BKC + row) * N + n0 + ch * 8;
            uint32_t bdst = bBase + s * stageB + (uint32_t)((row * HBN + ch * 8) * 2);
            CP_A16(bdst, bsrc);
        }
    };

    ld_async(0, 0); CP_COMMIT();

    for (int c = 0; c < NC; c++) {
        const int s = c & 1;
        CP_WAIT(0);
        __syncthreads();
        if (c + 1 < NC) { ld_async(c + 1, s ^ 1); CP_COMMIT(); }

#pragma unroll
        for (int ks = 0; ks < 4; ks++) {
            uint32_t afr[4][4];
#pragma unroll
            for (int mt = 0; mt < 4; mt++)
                ldsm_x4(afr[mt], aAddr + s * stageA + ks * 32 + mt * (16 * HAK * 2));
#pragma unroll
            for (int nbp = 0; nbp < 2; nbp++) {
                uint32_t b4[4];
                ldsm_x4t(b4, bAddr + s * stageB + ks * (16 * HBN * 2) + nbp * 32);
#pragma unroll
                for (int mt = 0; mt < 4; mt++) {
                    mma_f16(acc[mt][2 * nbp],     afr[mt], b4[0], b4[1]);
                    mma_f16(acc[mt][2 * nbp + 1], afr[mt], b4[2], b4[3]);
                }
            }
        }
    }

#pragma unroll
    for (int mt = 0; mt < 4; mt++) {
        int r0 = m0 + wm * 64 + mt * 16 + g;
#pragma unroll
        for (int nt = 0; nt < 4; nt++) {
            int c0 = n0 + wn * 32 + nt * 8 + q * 2;
            if (HALF_OUT) {
                __half* C = (__half*)Cv;
                *(__half2*)&C[(size_t)r0 * N + c0] =
                    __floats2half2_rn(acc[mt][nt][0], acc[mt][nt][1]);
                *(__half2*)&C[(size_t)(r0 + 8) * N + c0] =
                    __floats2half2_rn(acc[mt][nt][2], acc[mt][nt][3]);
            } else {
                float* C = (float*)Cv;
                *(float2*)&C[(size_t)r0 * N + c0]       = make_float2(acc[mt][nt][0], acc[mt][nt][1]);
                *(float2*)&C[(size_t)(r0 + 8) * N + c0] = make_float2(acc[mt][nt][2], acc[mt][nt][3]);
            }
        }
    }
}

// ---------------------------------------------------------------------------
// Flash attention v2: fp16 mma + ldmatrix, triple-buffered cp.async K/V.
// Softmax: exp via ex2.approx.f16x2 (half the MUFU ops, direct P store);
// row-sum l via ones-column MMA in the PV loop (no FADD chain, no shfl).
// ---------------------------------------------------------------------------
#define FST 72
#define NQT (SEQ/128)
#define KVST (2 * 64 * FST)   // halves per KV stage (K then V)
#define FLASH_SMEM ((128*FST + 3*KVST + 4*32*FST) * 2)

__global__ __launch_bounds__(128) void flash_f16(const __half* __restrict__ qkv,
                                                 __half* __restrict__ attn_out) {
    extern __shared__ __half smh[];
    __half* Qs = smh;
    __half* KV = Qs + 128 * FST;
    __half* Ps = KV + 3 * KVST;

    const int tid  = threadIdx.x;
    const int lane = tid & 31;
    const int w    = tid >> 5;
    const int g    = lane >> 2;
    const int q    = lane & 3;

    const int bh = blockIdx.y;
    const int b  = bh >> 4;
    const int h  = bh & 15;

    const float LOG2E  = 1.44269504088896f;
    const float scale2 = 0.125f * LOG2E;
    const float slope2 = exp2f(-0.5f * (float)(h + 1)) * LOG2E;
    const uint32_t ONES = 0x3C003C00u;   // half2(1,1)

    const __half* qb = qkv + (size_t)b * SEQ * (3 * DIM) + h * DH;
    const __half* kb = qb + DIM;
    const __half* vb = qb + 2 * DIM;

    __half* Pw = Ps + w * 32 * FST;

    const uint32_t sQ = smem_u32(Qs), sKV = smem_u32(KV), sP = smem_u32(Pw);
    const int l15 = lane & 15, lhi = lane >> 4;
    const uint32_t qA = sQ + (uint32_t)(((w * 32 + l15) * FST + lhi * 8) * 2);
    const uint32_t pA = sP + (uint32_t)((l15 * FST + lhi * 8) * 2);
    const uint32_t kBr = sKV + (uint32_t)((((lane & 7) + ((lane >> 4) << 3)) * FST
                                          + ((lane >> 3) & 1) * 8) * 2);
    const uint32_t vBr = sKV + (uint32_t)(64 * FST * 2) +
                         (uint32_t)((l15 * FST + lhi * 8) * 2);

    const int qi = NQT - 1 - blockIdx.x;    // big tiles first
    const int q0 = qi * 128;

    {
        const __half* src = qb + (size_t)(q0 + tid) * (3 * DIM);
        __half* dst = Qs + tid * FST;
#pragma unroll
        for (int c = 0; c < 8; c++)
            *(uint4*)(dst + c * 8) = *(const uint4*)(src + c * 8);
    }

    const int kvr = tid >> 1, kvc = (tid & 1) * 32;
    auto ld_kv = [&](int kt, int s) {
        const int k0_ = kt * 64;
        const __half* ksrc = kb + (size_t)(k0_ + kvr) * (3 * DIM) + kvc;
        const __half* vsrc = vb + (size_t)(k0_ + kvr) * (3 * DIM) + kvc;
        uint32_t kdst = sKV + (uint32_t)(s * KVST * 2) + (uint32_t)((kvr * FST + kvc) * 2);
        uint32_t vdst = kdst + (uint32_t)(64 * FST * 2);
#pragma unroll
        for (int j = 0; j < 4; j++) {
            CP_A16(kdst + j * 16, ksrc + j * 8);
            CP_A16(vdst + j * 16, vsrc + j * 8);
        }
    };

    float o[2][8][4];
    float mprev[2][2], lrun[2][2];
#pragma unroll
    for (int mt = 0; mt < 2; mt++) {
        mprev[mt][0] = mprev[mt][1] = -1e30f;
        lrun[mt][0]  = lrun[mt][1]  = 0.f;
#pragma unroll
        for (int nt = 0; nt < 8; nt++)
#pragma unroll
            for (int r = 0; r < 4; r++) o[mt][nt][r] = 0.f;
    }

    const int nkt = 2 * qi + 2;
    const int wrow_min = q0 + w * 32;
    const int wrow_max = wrow_min + 31;

    ld_kv(0, 0); CP_COMMIT();
    if (nkt > 1) { ld_kv(1, 1); CP_COMMIT(); }

    for (int kt = 0; kt < nkt; kt++) {
        const int s = kt % 3;
        const int k0 = kt * 64;
        if (kt + 1 < nkt) { CP_WAIT(1); } else { CP_WAIT(0); }
        __syncthreads();
        if (kt + 2 < nkt) { ld_kv(kt + 2, (kt + 2) % 3); CP_COMMIT(); }

        if (k0 > wrow_max) continue;

        const uint32_t kB = kBr + (uint32_t)(s * KVST * 2);
        const uint32_t vB = vBr + (uint32_t)(s * KVST * 2);

        // ---- S = Q @ K^T ----
        float sreg[2][8][4];
#pragma unroll
        for (int mt = 0; mt < 2; mt++)
#pragma unroll
            for (int nt = 0; nt < 8; nt++)
#pragma unroll
                for (int r = 0; r < 4; r++) sreg[mt][nt][r] = 0.f;

#pragma unroll
        for (int ks = 0; ks < 4; ks++) {
            uint32_t afr[2][4];
            ldsm_x4(afr[0], qA + ks * 32);
            ldsm_x4(afr[1], qA + ks * 32 + 16 * FST * 2);
#pragma unroll
            for (int nbp = 0; nbp < 4; nbp++) {
                uint32_t b4[4];
                ldsm_x4(b4, kB + nbp * 16 * FST * 2 + ks * 32);
                mma_f16(sreg[0][2 * nbp],     afr[0], b4[0], b4[1]);
                mma_f16(sreg[1][2 * nbp],     afr[1], b4[0], b4[1]);
                mma_f16(sreg[0][2 * nbp + 1], afr[0], b4[2], b4[3]);
                mma_f16(sreg[1][2 * nbp + 1], afr[1], b4[2], b4[3]);
            }
        }

        // ---- bias + mask + online softmax (base-2, half2 exp) ----
        const bool need_mask = (k0 + 63 > wrow_min);
#pragma unroll
        for (int mt = 0; mt < 2; mt++) {
            const int r0 = wrow_min + mt * 16 + g;
            const int r1 = r0 + 8;
            float mx0 = -1e30f, mx1 = -1e30f;
#pragma unroll
            for (int nt = 0; nt < 8; nt++) {
#pragma unroll
                for (int jj = 0; jj < 2; jj++) {
                    int col = k0 + nt * 8 + q * 2 + jj;
                    float bias = slope2 * (float)col;
                    float v0 = fmaf(sreg[mt][nt][jj],     scale2, bias);
                    float v1 = fmaf(sreg[mt][nt][2 + jj], scale2, bias);
                    if (need_mask) {
                        if (col > r0) v0 = -1e30f;
                        if (col > r1) v1 = -1e30f;
                    }
                    sreg[mt][nt][jj]     = v0;
                    sreg[mt][nt][2 + jj] = v1;
                    mx0 = fmaxf(mx0, v0);
                    mx1 = fmaxf(mx1, v1);
                }
            }
            mx0 = fmaxf(mx0, __shfl_xor_sync(0xffffffffu, mx0, 1));
            mx0 = fmaxf(mx0, __shfl_xor_sync(0xffffffffu, mx0, 2));
            mx1 = fmaxf(mx1, __shfl_xor_sync(0xffffffffu, mx1, 1));
            mx1 = fmaxf(mx1, __shfl_xor_sync(0xffffffffu, mx1, 2));

            float mn0 = fmaxf(mprev[mt][0], mx0);
            float mn1 = fmaxf(mprev[mt][1], mx1);
            float al0 = ex2f(mprev[mt][0] - mn0);
            float al1 = ex2f(mprev[mt][1] - mn1);
            lrun[mt][0] *= al0;
            lrun[mt][1] *= al1;
            mprev[mt][0] = mn0;
            mprev[mt][1] = mn1;
#pragma unroll
            for (int nt = 0; nt < 8; nt++) {
                o[mt][nt][0] *= al0;
                o[mt][nt][1] *= al0;
                o[mt][nt][2] *= al1;
                o[mt][nt][3] *= al1;
            }

            // exp in f16x2 + direct P store (P is fp16 anyway)
#pragma unroll
            for (int nt = 0; nt < 8; nt++) {
                uint32_t h0 = ex2_h2(sreg[mt][nt][1] - mn0, sreg[mt][nt][0] - mn0);
                uint32_t h1 = ex2_h2(sreg[mt][nt][3] - mn1, sreg[mt][nt][2] - mn1);
                *(uint32_t*)&Pw[(mt * 16 + g)     * FST + nt * 8 + q * 2] = h0;
                *(uint32_t*)&Pw[(mt * 16 + g + 8) * FST + nt * 8 + q * 2] = h1;
            }
        }
        __syncwarp();

        // ---- O += P @ V  (+ row-sum l via ones-column MMA) ----
        float ls[2][4];
#pragma unroll
        for (int mt = 0; mt < 2; mt++)
#pragma unroll
            for (int r = 0; r < 4; r++) ls[mt][r] = 0.f;

#pragma unroll
        for (int ks = 0; ks < 4; ks++) {
            uint32_t afr[2][4];
            ldsm_x4(afr[0], pA + ks * 32);
            ldsm_x4(afr[1], pA + ks * 32 + 16 * FST * 2);
            mma_f16(ls[0], afr[0], ONES, ONES);
            mma_f16(ls[1], afr[1], ONES, ONES);
#pragma unroll
            for (int nbp = 0; nbp < 4; nbp++) {
                uint32_t b4[4];
                ldsm_x4t(b4, vB + ks * 16 * FST * 2 + nbp * 32);
                mma_f16(o[0][2 * nbp],     afr[0], b4[0], b4[1]);
                mma_f16(o[1][2 * nbp],     afr[1], b4[0], b4[1]);
                mma_f16(o[0][2 * nbp + 1], afr[0], b4[2], b4[3]);
                mma_f16(o[1][2 * nbp + 1], afr[1], b4[2], b4[3]);
            }
        }
        lrun[0][0] += ls[0][0];
        lrun[0][1] += ls[0][2];
        lrun[1][0] += ls[1][0];
        lrun[1][1] += ls[1][2];
    }

    // ---- epilogue ----
#pragma unroll
    for (int mt = 0; mt < 2; mt++) {
        float inv0 = 1.f / lrun[mt][0];
        float inv1 = 1.f / lrun[mt][1];
        int r0 = q0 + w * 32 + mt * 16 + g;
#pragma unroll
        for (int nt = 0; nt < 8; nt++) {
            int c = h * DH + nt * 8 + q * 2;
            *(__half2*)&attn_out[(size_t)(b * SEQ + r0) * DIM + c] =
                __floats2half2_rn(o[mt][nt][0] * inv0, o[mt][nt][1] * inv0);
            *(__half2*)&attn_out[(size_t)(b * SEQ + r0 + 8) * DIM + c] =
                __floats2half2_rn(o[mt][nt][2] * inv1, o[mt][nt][3] * inv1);
        }
    }
}

// ---------------------------------------------------------------------------
extern "C" void kernel_launch(void* const* d_in, const int* in_sizes, int n_in,
                              void* d_out, int out_size) {
    const float* x      = (const float*)d_in[0];
    const float* w_qkv  = (const float*)d_in[1];
    const float* w_proj = (const float*)d_in[2];
    float* out = (float*)d_out;

    __half *xh, *wqkvh, *wprojh, *qkv, *attn;
    cudaGetSymbolAddress((void**)&xh, g_xh);
    cudaGetSymbolAddress((void**)&wqkvh, g_wqkv_h);
    cudaGetSymbolAddress((void**)&wprojh, g_wproj_h);
    cudaGetSymbolAddress((void**)&qkv, g_qkv);
    cudaGetSymbolAddress((void**)&attn, g_attn);

    cudaFuncSetAttribute(flash_f16, cudaFuncAttributeMaxDynamicSharedMemorySize,
                         (int)FLASH_SMEM);

    // 0) convert inputs to half
    cvt_half_kernel<<<(MTOT * DIM) / 1024, 256>>>((const float4*)x, (uint2*)xh);
    cvt_half_kernel<<<(DIM * 3 * DIM) / 1024, 256>>>((const float4*)w_qkv, (uint2*)wqkvh);
    cvt_half_kernel<<<(DIM * DIM) / 1024, 256>>>((const float4*)w_proj, (uint2*)wprojh);

    // 1) qkv = x @ w_qkv  (half out)
    hgemm<true><<<dim3(3 * DIM / 128, MTOT / 128), 256>>>(xh, wqkvh, qkv, 3 * DIM, DIM);

    // 2) attention
    flash_f16<<<dim3(NQT, BATCH * HEADS), 128, FLASH_SMEM>>>(qkv, attn);

    // 3) out = attn @ w_proj  (float out)
    hgemm<false><<<dim3(DIM / 128, MTOT / 128), 256>>>(attn, wprojh, out, DIM, DIM);
}

// round 17
// speedup vs baseline: 1.1264x; 1.0353x over previous
#include <cuda_runtime.h>
#include <cuda_fp16.h>
#include <math.h>
#include <stdint.h>

// Problem constants
#define BATCH 2
#define SEQ   2048
#define DIM   1024
#define HEADS 16
#define DH    64
#define MTOT  (BATCH*SEQ)          // 4096 rows

// Scratch (allocation-free rule: __device__ globals)
__device__ __half g_xh[(size_t)MTOT * DIM];
__device__ __half g_wqkv_h[(size_t)DIM * 3 * DIM];
__device__ __half g_wproj_h[(size_t)DIM * DIM];
__device__ __half g_qkv[(size_t)MTOT * 3 * DIM];
__device__ __half g_attn[(size_t)MTOT * DIM];

// ---------------------------------------------------------------------------
// PTX helpers
// ---------------------------------------------------------------------------
__device__ __forceinline__ uint32_t smem_u32(const void* p) {
    uint32_t a;
    asm("{ .reg .u64 t; cvta.to.shared.u64 t, %1; cvt.u32.u64 %0, t; }" : "=r"(a) : "l"(p));
    return a;
}

__device__ __forceinline__ void ldsm_x4(uint32_t r[4], uint32_t addr) {
    asm volatile("ldmatrix.sync.aligned.m8n8.x4.shared.b16 {%0,%1,%2,%3}, [%4];"
                 : "=r"(r[0]), "=r"(r[1]), "=r"(r[2]), "=r"(r[3]) : "r"(addr));
}
__device__ __forceinline__ void ldsm_x4t(uint32_t r[4], uint32_t addr) {
    asm volatile("ldmatrix.sync.aligned.m8n8.x4.trans.shared.b16 {%0,%1,%2,%3}, [%4];"
                 : "=r"(r[0]), "=r"(r[1]), "=r"(r[2]), "=r"(r[3]) : "r"(addr));
}
__device__ __forceinline__ void mma_f16(float c[4], const uint32_t a[4],
                                        uint32_t b0, uint32_t b1) {
    asm volatile(
        "mma.sync.aligned.m16n8k16.row.col.f32.f16.f16.f32 "
        "{%0,%1,%2,%3}, {%4,%5,%6,%7}, {%8,%9}, {%0,%1,%2,%3};"
        : "+f"(c[0]), "+f"(c[1]), "+f"(c[2]), "+f"(c[3])
        : "r"(a[0]), "r"(a[1]), "r"(a[2]), "r"(a[3]), "r"(b0), "r"(b1));
}
__device__ __forceinline__ float ex2f(float x) {
    float r;
    asm("ex2.approx.ftz.f32 %0, %1;" : "=f"(r) : "f"(x));
    return r;
}
// pack (lo,hi) fp32 pair -> f16x2, then exp2 in half2 (one MUFU op per 2 els)
__device__ __forceinline__ uint32_t ex2_h2(float hi, float lo) {
    uint32_t h;
    asm("{\n\tcvt.rn.f16x2.f32 %0, %1, %2;\n\tex2.approx.f16x2 %0, %0;\n\t}"
        : "=r"(h) : "f"(hi), "f"(lo));
    return h;
}

#define CP_A16(dst, src) \
    asm volatile("cp.async.cg.shared.global [%0], [%1], 16;" :: "r"(dst), "l"(src))
#define CP_COMMIT() asm volatile("cp.async.commit_group;" ::: "memory")
#define CP_WAIT(n)  asm volatile("cp.async.wait_group %0;" :: "n"(n) : "memory")

// ---------------------------------------------------------------------------
// fp32 -> fp16 conversion pre-pass, single merged launch for x, w_qkv, w_proj
// ---------------------------------------------------------------------------
#define X4CNT  ((MTOT * DIM) / 4)          // 1048576 float4s
#define WQ4CNT ((DIM * 3 * DIM) / 4)       // 786432
#define WP4CNT ((DIM * DIM) / 4)           // 262144
#define CVT_BLOCKS ((X4CNT + WQ4CNT + WP4CNT) / 256)

__global__ __launch_bounds__(256) void cvt_all_kernel(const float4* __restrict__ x,
                                                      uint2* __restrict__ xh,
                                                      const float4* __restrict__ wq,
                                                      uint2* __restrict__ wqh,
                                                      const float4* __restrict__ wp,
                                                      uint2* __restrict__ wph) {
    int i = blockIdx.x * 256 + threadIdx.x;
    const float4* src;
    uint2* dst;
    if (i < X4CNT) {
        src = x; dst = xh;
    } else if (i < X4CNT + WQ4CNT) {
        i -= X4CNT; src = wq; dst = wqh;
    } else {
        i -= X4CNT + WQ4CNT; src = wp; dst = wph;
    }
    float4 v = src[i];
    __half2 a = __floats2half2_rn(v.x, v.y);
    __half2 b = __floats2half2_rn(v.z, v.w);
    dst[i] = make_uint2(*(uint32_t*)&a, *(uint32_t*)&b);
}

// ---------------------------------------------------------------------------
// FP16 tensor-core GEMM (best known, FROZEN): 256 threads, 8 warps (2m x 4n),
// warp tile 64x32, BK=64, 2-stage cp.async.
// ---------------------------------------------------------------------------
#define HAK 72
#define HBN 136
#define NST 2
#define BKC 64

template <bool HALF_OUT>
__global__ __launch_bounds__(256, 2) void hgemm(const __half* __restrict__ A,
                                                const __half* __restrict__ B,
                                                void* __restrict__ Cv,
                                                int N, int K) {
    __shared__ __half As[NST][128][HAK];   // [m][k]
    __shared__ __half Bs[NST][BKC][HBN];   // [k][n]

    const int tid  = threadIdx.x;
    const int lane = tid & 31;
    const int wid  = tid >> 5;
    const int wm   = wid & 1;
    const int wn   = wid >> 1;
    const int g    = lane >> 2;
    const int q    = lane & 3;

    const int m0 = blockIdx.y * 128;
    const int n0 = blockIdx.x * 128;

    float acc[4][4][4];
#pragma unroll
    for (int i = 0; i < 4; i++)
#pragma unroll
        for (int j = 0; j < 4; j++)
#pragma unroll
            for (int r = 0; r < 4; r++) acc[i][j][r] = 0.f;

    const int NC = K / BKC;

    const uint32_t aBase = smem_u32(&As[0][0][0]);
    const uint32_t bBase = smem_u32(&Bs[0][0][0]);
    const uint32_t stageA = 128 * HAK * 2;
    const uint32_t stageB = BKC * HBN * 2;

    const int l15 = lane & 15, lhi = lane >> 4;
    const uint32_t aAddr = aBase + (uint32_t)(((wm * 64 + l15) * HAK + lhi * 8) * 2);
    const uint32_t bAddr = bBase + (uint32_t)((l15 * HBN + wn * 32 + lhi * 8) * 2);

    const int arow = tid >> 1;
    const int ach  = (tid & 1) * 32;
    const __half* Arow = A + (size_t)(m0 + arow) * K + ach;
    auto ld_async = [&](int c, int s) {
        const __half* asrc = Arow + c * BKC;
        uint32_t adst = aBase + s * stageA + (uint32_t)((arow * HAK + ach) * 2);
#pragma unroll
        for (int i = 0; i < 4; i++)
            CP_A16(adst + i * 16, asrc + i * 8);
#pragma unroll
        for (int i = 0; i < 4; i++) {
            int idx = tid + i * 256;
            int row = idx >> 4, ch = idx & 15;
            const __half* bsrc = B + (size_t)(c * BKC + row) * N + n0 + ch * 8;
            uint32_t bdst = bBase + s * stageB + (uint32_t)((row * HBN + ch * 8) * 2);
            CP_A16(bdst, bsrc);
        }
    };

    ld_async(0, 0); CP_COMMIT();

    for (int c = 0; c < NC; c++) {
        const int s = c & 1;
        CP_WAIT(0);
        __syncthreads();
        if (c + 1 < NC) { ld_async(c + 1, s ^ 1); CP_COMMIT(); }

#pragma unroll
        for (int ks = 0; ks < 4; ks++) {
            uint32_t afr[4][4];
#pragma unroll
            for (int mt = 0; mt < 4; mt++)
                ldsm_x4(afr[mt], aAddr + s * stageA + ks * 32 + mt * (16 * HAK * 2));
#pragma unroll
            for (int nbp = 0; nbp < 2; nbp++) {
                uint32_t b4[4];
                ldsm_x4t(b4, bAddr + s * stageB + ks * (16 * HBN * 2) + nbp * 32);
#pragma unroll
                for (int mt = 0; mt < 4; mt++) {
                    mma_f16(acc[mt][2 * nbp],     afr[mt], b4[0], b4[1]);
                    mma_f16(acc[mt][2 * nbp + 1], afr[mt], b4[2], b4[3]);
                }
            }
        }
    }

#pragma unroll
    for (int mt = 0; mt < 4; mt++) {
        int r0 = m0 + wm * 64 + mt * 16 + g;
#pragma unroll
        for (int nt = 0; nt < 4; nt++) {
            int c0 = n0 + wn * 32 + nt * 8 + q * 2;
            if (HALF_OUT) {
                __half* C = (__half*)Cv;
                *(__half2*)&C[(size_t)r0 * N + c0] =
                    __floats2half2_rn(acc[mt][nt][0], acc[mt][nt][1]);
                *(__half2*)&C[(size_t)(r0 + 8) * N + c0] =
                    __floats2half2_rn(acc[mt][nt][2], acc[mt][nt][3]);
            } else {
                float* C = (float*)Cv;
                *(float2*)&C[(size_t)r0 * N + c0]       = make_float2(acc[mt][nt][0], acc[mt][nt][1]);
                *(float2*)&C[(size_t)(r0 + 8) * N + c0] = make_float2(acc[mt][nt][2], acc[mt][nt][3]);
            }
        }
    }
}

// ---------------------------------------------------------------------------
// Flash attention v3: P NEVER touches smem.
// The ex2.f16x2 packed outputs (c0c1 = row g, c2c3 = row g+8 pairs) ARE the
// m16n8k16 A-fragments for the PV mma:
//   k16-slice ks: A = { h_lo[2ks], h_hi[2ks], h_lo[2ks+1], h_hi[2ks+1] }.
// Removes 16 STS + 8 ldsm + syncwarp per warp-tile and 9KB smem.
// ---------------------------------------------------------------------------
#define FST 72
#define NQT (SEQ/128)
#define KVST (2 * 64 * FST)   // halves per KV stage (K then V)
#define FLASH_SMEM ((128*FST + 3*KVST) * 2)

__global__ __launch_bounds__(128) void flash_f16(const __half* __restrict__ qkv,
                                                 __half* __restrict__ attn_out) {
    extern __shared__ __half smh[];
    __half* Qs = smh;
    __half* KV = Qs + 128 * FST;

    const int tid  = threadIdx.x;
    const int lane = tid & 31;
    const int w    = tid >> 5;
    const int g    = lane >> 2;
    const int q    = lane & 3;

    const int bh = blockIdx.y;
    const int b  = bh >> 4;
    const int h  = bh & 15;

    const float LOG2E  = 1.44269504088896f;
    const float scale2 = 0.125f * LOG2E;
    const float slope2 = exp2f(-0.5f * (float)(h + 1)) * LOG2E;
    const uint32_t ONES = 0x3C003C00u;   // half2(1,1)

    const __half* qb = qkv + (size_t)b * SEQ * (3 * DIM) + h * DH;
    const __half* kb = qb + DIM;
    const __half* vb = qb + 2 * DIM;

    const uint32_t sQ = smem_u32(Qs), sKV = smem_u32(KV);
    const int l15 = lane & 15, lhi = lane >> 4;
    const uint32_t qA = sQ + (uint32_t)(((w * 32 + l15) * FST + lhi * 8) * 2);
    const uint32_t kBr = sKV + (uint32_t)((((lane & 7) + ((lane >> 4) << 3)) * FST
                                          + ((lane >> 3) & 1) * 8) * 2);
    const uint32_t vBr = sKV + (uint32_t)(64 * FST * 2) +
                         (uint32_t)((l15 * FST + lhi * 8) * 2);

    const int qi = NQT - 1 - blockIdx.x;    // big tiles first
    const int q0 = qi * 128;

    {
        const __half* src = qb + (size_t)(q0 + tid) * (3 * DIM);
        __half* dst = Qs + tid * FST;
#pragma unroll
        for (int c = 0; c < 8; c++)
            *(uint4*)(dst + c * 8) = *(const uint4*)(src + c * 8);
    }

    const int kvr = tid >> 1, kvc = (tid & 1) * 32;
    auto ld_kv = [&](int kt, int s) {
        const int k0_ = kt * 64;
        const __half* ksrc = kb + (size_t)(k0_ + kvr) * (3 * DIM) + kvc;
        const __half* vsrc = vb + (size_t)(k0_ + kvr) * (3 * DIM) + kvc;
        uint32_t kdst = sKV + (uint32_t)(s * KVST * 2) + (uint32_t)((kvr * FST + kvc) * 2);
        uint32_t vdst = kdst + (uint32_t)(64 * FST * 2);
#pragma unroll
        for (int j = 0; j < 4; j++) {
            CP_A16(kdst + j * 16, ksrc + j * 8);
            CP_A16(vdst + j * 16, vsrc + j * 8);
        }
    };

    float o[2][8][4];
    float mprev[2][2], lrun[2][2];
#pragma unroll
    for (int mt = 0; mt < 2; mt++) {
        mprev[mt][0] = mprev[mt][1] = -1e30f;
        lrun[mt][0]  = lrun[mt][1]  = 0.f;
#pragma unroll
        for (int nt = 0; nt < 8; nt++)
#pragma unroll
            for (int r = 0; r < 4; r++) o[mt][nt][r] = 0.f;
    }

    const int nkt = 2 * qi + 2;
    const int wrow_min = q0 + w * 32;
    const int wrow_max = wrow_min + 31;

    ld_kv(0, 0); CP_COMMIT();
    if (nkt > 1) { ld_kv(1, 1); CP_COMMIT(); }

    for (int kt = 0; kt < nkt; kt++) {
        const int s = kt % 3;
        const int k0 = kt * 64;
        if (kt + 1 < nkt) { CP_WAIT(1); } else { CP_WAIT(0); }
        __syncthreads();
        if (kt + 2 < nkt) { ld_kv(kt + 2, (kt + 2) % 3); CP_COMMIT(); }

        if (k0 > wrow_max) continue;

        const uint32_t kB = kBr + (uint32_t)(s * KVST * 2);
        const uint32_t vB = vBr + (uint32_t)(s * KVST * 2);

        // ---- S = Q @ K^T ----
        float sreg[2][8][4];
#pragma unroll
        for (int mt = 0; mt < 2; mt++)
#pragma unroll
            for (int nt = 0; nt < 8; nt++)
#pragma unroll
                for (int r = 0; r < 4; r++) sreg[mt][nt][r] = 0.f;

#pragma unroll
        for (int ks = 0; ks < 4; ks++) {
            uint32_t afr[2][4];
            ldsm_x4(afr[0], qA + ks * 32);
            ldsm_x4(afr[1], qA + ks * 32 + 16 * FST * 2);
#pragma unroll
            for (int nbp = 0; nbp < 4; nbp++) {
                uint32_t b4[4];
                ldsm_x4(b4, kB + nbp * 16 * FST * 2 + ks * 32);
                mma_f16(sreg[0][2 * nbp],     afr[0], b4[0], b4[1]);
                mma_f16(sreg[1][2 * nbp],     afr[1], b4[0], b4[1]);
                mma_f16(sreg[0][2 * nbp + 1], afr[0], b4[2], b4[3]);
                mma_f16(sreg[1][2 * nbp + 1], afr[1], b4[2], b4[3]);
            }
        }

        // ---- bias + mask + online softmax (base-2, half2 exp, P in regs) ----
        const bool need_mask = (k0 + 63 > wrow_min);
        uint32_t pexp[2][8][2];   // [mt][nt][0]=c0c1 pair (row g), [1]=c2c3 (row g+8)
#pragma unroll
        for (int mt = 0; mt < 2; mt++) {
            const int r0 = wrow_min + mt * 16 + g;
            const int r1 = r0 + 8;
            float mx0 = -1e30f, mx1 = -1e30f;
#pragma unroll
            for (int nt = 0; nt < 8; nt++) {
#pragma unroll
                for (int jj = 0; jj < 2; jj++) {
                    int col = k0 + nt * 8 + q * 2 + jj;
                    float bias = slope2 * (float)col;
                    float v0 = fmaf(sreg[mt][nt][jj],     scale2, bias);
                    float v1 = fmaf(sreg[mt][nt][2 + jj], scale2, bias);
                    if (need_mask) {
                        if (col > r0) v0 = -1e30f;
                        if (col > r1) v1 = -1e30f;
                    }
                    sreg[mt][nt][jj]     = v0;
                    sreg[mt][nt][2 + jj] = v1;
                    mx0 = fmaxf(mx0, v0);
                    mx1 = fmaxf(mx1, v1);
                }
            }
            mx0 = fmaxf(mx0, __shfl_xor_sync(0xffffffffu, mx0, 1));
            mx0 = fmaxf(mx0, __shfl_xor_sync(0xffffffffu, mx0, 2));
            mx1 = fmaxf(mx1, __shfl_xor_sync(0xffffffffu, mx1, 1));
            mx1 = fmaxf(mx1, __shfl_xor_sync(0xffffffffu, mx1, 2));

            float mn0 = fmaxf(mprev[mt][0], mx0);
            float mn1 = fmaxf(mprev[mt][1], mx1);
            float al0 = ex2f(mprev[mt][0] - mn0);
            float al1 = ex2f(mprev[mt][1] - mn1);
            lrun[mt][0] *= al0;
            lrun[mt][1] *= al1;
            mprev[mt][0] = mn0;
            mprev[mt][1] = mn1;
#pragma unroll
            for (int nt = 0; nt < 8; nt++) {
                o[mt][nt][0] *= al0;
                o[mt][nt][1] *= al0;
                o[mt][nt][2] *= al1;
                o[mt][nt][3] *= al1;
            }

            // exp in f16x2 -> packed P fragments kept in registers
#pragma unroll
            for (int nt = 0; nt < 8; nt++) {
                pexp[mt][nt][0] = ex2_h2(sreg[mt][nt][1] - mn0, sreg[mt][nt][0] - mn0);
                pexp[mt][nt][1] = ex2_h2(sreg[mt][nt][3] - mn1, sreg[mt][nt][2] - mn1);
            }
        }

        // ---- O += P @ V  (P A-fragments direct from pexp; + l via ones-MMA) ----
        float ls[2][4];
#pragma unroll
        for (int mt = 0; mt < 2; mt++)
#pragma unroll
            for (int r = 0; r < 4; r++) ls[mt][r] = 0.f;

#pragma unroll
        for (int ks = 0; ks < 4; ks++) {
            uint32_t afr[2][4];
#pragma unroll
            for (int mt = 0; mt < 2; mt++) {
                afr[mt][0] = pexp[mt][2 * ks][0];
                afr[mt][1] = pexp[mt][2 * ks][1];
                afr[mt][2] = pexp[mt][2 * ks + 1][0];
                afr[mt][3] = pexp[mt][2 * ks + 1][1];
            }
            mma_f16(ls[0], afr[0], ONES, ONES);
            mma_f16(ls[1], afr[1], ONES, ONES);
#pragma unroll
            for (int nbp = 0; nbp < 4; nbp++) {
                uint32_t b4[4];
                ldsm_x4t(b4, vB + ks * 16 * FST * 2 + nbp * 32);
                mma_f16(o[0][2 * nbp],     afr[0], b4[0], b4[1]);
                mma_f16(o[1][2 * nbp],     afr[1], b4[0], b4[1]);
                mma_f16(o[0][2 * nbp + 1], afr[0], b4[2], b4[3]);
                mma_f16(o[1][2 * nbp + 1], afr[1], b4[2], b4[3]);
            }
        }
        lrun[0][0] += ls[0][0];
        lrun[0][1] += ls[0][2];
        lrun[1][0] += ls[1][0];
        lrun[1][1] += ls[1][2];
    }

    // ---- epilogue ----
#pragma unroll
    for (int mt = 0; mt < 2; mt++) {
        float inv0 = 1.f / lrun[mt][0];
        float inv1 = 1.f / lrun[mt][1];
        int r0 = q0 + w * 32 + mt * 16 + g;
#pragma unroll
        for (int nt = 0; nt < 8; nt++) {
            int c = h * DH + nt * 8 + q * 2;
            *(__half2*)&attn_out[(size_t)(b * SEQ + r0) * DIM + c] =
                __floats2half2_rn(o[mt][nt][0] * inv0, o[mt][nt][1] * inv0);
            *(__half2*)&attn_out[(size_t)(b * SEQ + r0 + 8) * DIM + c] =
                __floats2half2_rn(o[mt][nt][2] * inv1, o[mt][nt][3] * inv1);
        }
    }
}

// ---------------------------------------------------------------------------
extern "C" void kernel_launch(void* const* d_in, const int* in_sizes, int n_in,
                              void* d_out, int out_size) {
    const float* x      = (const float*)d_in[0];
    const float* w_qkv  = (const float*)d_in[1];
    const float* w_proj = (const float*)d_in[2];
    float* out = (float*)d_out;

    __half *xh, *wqkvh, *wprojh, *qkv, *attn;
    cudaGetSymbolAddress((void**)&xh, g_xh);
    cudaGetSymbolAddress((void**)&wqkvh, g_wqkv_h);
    cudaGetSymbolAddress((void**)&wprojh, g_wproj_h);
    cudaGetSymbolAddress((void**)&qkv, g_qkv);
    cudaGetSymbolAddress((void**)&attn, g_attn);

    cudaFuncSetAttribute(flash_f16, cudaFuncAttributeMaxDynamicSharedMemorySize,
                         (int)FLASH_SMEM);

    // 0) convert all inputs to half (single merged launch)
    cvt_all_kernel<<<CVT_BLOCKS, 256>>>((const float4*)x, (uint2*)xh,
                                        (const float4*)w_qkv, (uint2*)wqkvh,
                                        (const float4*)w_proj, (uint2*)wprojh);

    // 1) qkv = x @ w_qkv  (half out)
    hgemm<true><<<dim3(3 * DIM / 128, MTOT / 128), 256>>>(xh, wqkvh, qkv, 3 * DIM, DIM);

    // 2) attention
    flash_f16<<<dim3(NQT, BATCH * HEADS), 128, FLASH_SMEM>>>(qkv, attn);

    // 3) out = attn @ w_proj  (float out)
    hgemm<false><<<dim3(DIM / 128, MTOT / 128), 256>>>(attn, wprojh, out, DIM, DIM);
}